// round 15
// baseline (speedup 1.0000x reference)
#include <cuda_runtime.h>
#include <cuda_bf16.h>
#include <cuda_fp16.h>
#include <math.h>
#include <stdint.h>

#define NN   20000
#define EE   320000
#define ETOT (EE + NN)
#define HIDD 128
#define DD1  512
#define DD2  256

typedef __nv_bfloat16 bf16;

// ---------------- device scratch --------------------------------------------
__device__ __half g_xl1[(size_t)NN * DD1];
__device__ __half g_xr1[(size_t)NN * DD1];
__device__ __half g_xl2[(size_t)NN * DD2];
__device__ __half g_xr2[(size_t)NN * DD2];
__device__ bf16  g_xh [(size_t)NN * HIDD];
__device__ bf16  g_xlo[(size_t)NN * HIDD];
__device__ bf16  g_h1h[(size_t)NN * DD1];
__device__ bf16  g_h1l[(size_t)NN * DD1];
__device__ bf16  g_h2h[(size_t)NN * DD2];
__device__ bf16  g_h2l[(size_t)NN * DD2];
__device__ bf16  g_Wl1h[HIDD * DD1], g_Wl1l[HIDD * DD1];
__device__ bf16  g_Wr1h[HIDD * DD1], g_Wr1l[HIDD * DD1];
__device__ bf16  g_Wl2h[DD1 * DD2],  g_Wl2l[DD1 * DD2];
__device__ bf16  g_Wr2h[DD1 * DD2],  g_Wr2l[DD1 * DD2];
__device__ bf16  g_Wjkh[896 * HIDD], g_Wjkl[896 * HIDD];
__device__ int   g_rowptr[NN + 1];
__device__ int   g_cursor[NN];
__device__ int   g_colsrc[ETOT];

// ---------------- CSR build -------------------------------------------------
__global__ void init_hist_kernel() {
    int i = blockIdx.x * blockDim.x + threadIdx.x;
    if (i < NN) g_cursor[i] = 1;   // self loop per node
}

__global__ void hist_kernel(const int* __restrict__ ei) {
    int e = blockIdx.x * blockDim.x + threadIdx.x;
    if (e < EE) atomicAdd(&g_cursor[ei[EE + e]], 1);
}

__global__ void scan_kernel() {
    const int PER = 20;
    __shared__ int sh[1024];
    int t = threadIdx.x;
    int base = t * PER;
    int loc[PER];
    int sum = 0;
    #pragma unroll
    for (int i = 0; i < PER; i++) {
        int idx = base + i;
        int v = (idx < NN) ? g_cursor[idx] : 0;
        loc[i] = v;
        sum += v;
    }
    sh[t] = sum;
    __syncthreads();
    #pragma unroll
    for (int off = 1; off < 1024; off <<= 1) {
        int v = (t >= off) ? sh[t - off] : 0;
        __syncthreads();
        sh[t] += v;
        __syncthreads();
    }
    int run = sh[t] - sum;
    #pragma unroll
    for (int i = 0; i < PER; i++) {
        int idx = base + i;
        if (idx < NN) { g_rowptr[idx] = run; g_cursor[idx] = run; }
        run += loc[i];
    }
    if (t == 1023) g_rowptr[NN] = sh[1023];
}

__global__ void scatter_kernel(const int* __restrict__ ei) {
    int t = blockIdx.x * blockDim.x + threadIdx.x;
    if (t < EE) {
        int s = ei[t];
        int d = ei[EE + t];
        int pos = atomicAdd(&g_cursor[d], 1);
        g_colsrc[pos] = s;
    } else if (t < ETOT) {
        int i = t - EE;
        int pos = atomicAdd(&g_cursor[i], 1);
        g_colsrc[pos] = i;
    }
}

// ---------------- fp32 -> bf16 hi/lo split (3 jobs per launch) --------------
struct CvtJobs {
    const float* s[3];
    bf16* h[3];
    bf16* l[3];
    int   n[3];
};

__global__ void cvt_kernel(CvtJobs jobs) {
    int y = blockIdx.y;
    int n = jobs.n[y];
    int i = (blockIdx.x * blockDim.x + threadIdx.x) * 4;
    if (i >= n) return;
    const float* s = jobs.s[y];
    float4 v = *(const float4*)(s + i);
    bf16 hh[4], ll[4];
    hh[0] = __float2bfloat16_rn(v.x);
    hh[1] = __float2bfloat16_rn(v.y);
    hh[2] = __float2bfloat16_rn(v.z);
    hh[3] = __float2bfloat16_rn(v.w);
    ll[0] = __float2bfloat16_rn(v.x - __bfloat162float(hh[0]));
    ll[1] = __float2bfloat16_rn(v.y - __bfloat162float(hh[1]));
    ll[2] = __float2bfloat16_rn(v.z - __bfloat162float(hh[2]));
    ll[3] = __float2bfloat16_rn(v.w - __bfloat162float(hh[3]));
    *(uint2*)(jobs.h[y] + i) = *(uint2*)hh;
    *(uint2*)(jobs.l[y] + i) = *(uint2*)ll;
}

// ---------------- shared GEMM plumbing ---------------------------------------
__device__ __forceinline__ uint32_t smem_u32(const void* p) {
    return (uint32_t)__cvta_generic_to_shared(p);
}

__device__ __forceinline__ void cp16(uint32_t dst, const void* src, uint32_t sz) {
    asm volatile("cp.async.cg.shared.global [%0], [%1], 16, %2;"
                 :: "r"(dst), "l"(src), "r"(sz) : "memory");
}
#define CP_COMMIT() asm volatile("cp.async.commit_group;" ::: "memory")
#define CP_WAIT1()  asm volatile("cp.async.wait_group 1;" ::: "memory")

#define LDSM_X4(r, addr) \
    asm volatile("ldmatrix.sync.aligned.m8n8.x4.shared.b16 {%0,%1,%2,%3}, [%4];" \
        : "=r"((r)[0]), "=r"((r)[1]), "=r"((r)[2]), "=r"((r)[3]) : "r"(addr))

#define LDSM_X2T(r, addr) \
    asm volatile("ldmatrix.sync.aligned.m8n8.x2.trans.shared.b16 {%0,%1}, [%2];" \
        : "=r"((r)[0]), "=r"((r)[1]) : "r"(addr))

#define MMA16816(d, a, b) \
    asm volatile("mma.sync.aligned.m16n8k16.row.col.f32.bf16.bf16.f32 " \
        "{%0,%1,%2,%3},{%4,%5,%6,%7},{%8,%9},{%0,%1,%2,%3};" \
        : "+f"((d)[0]), "+f"((d)[1]), "+f"((d)[2]), "+f"((d)[3]) \
        : "r"((a)[0]), "r"((a)[1]), "r"((a)[2]), "r"((a)[3]), \
          "r"((b)[0]), "r"((b)[1]))

// ---------------- dual-output bf16 GEMM (3-term split), fp16 out ------------
#define STG_D   32768
#define GSMEM_D (3 * STG_D)

__global__ __launch_bounds__(256, 2)
void gemm_dual(const bf16* __restrict__ Ah, const bf16* __restrict__ Al,
               const bf16* __restrict__ B0h, const bf16* __restrict__ B0l,
               const bf16* __restrict__ B1h, const bf16* __restrict__ B1l,
               const float* __restrict__ b0, const float* __restrict__ b1,
               __half* __restrict__ C0, __half* __restrict__ C1,
               int M, int K, int Nhalf, int nHalfTiles)
{
    extern __shared__ char sm[];
    const uint32_t sb = smem_u32(sm);
    const int tid = threadIdx.x;
    const int lane = tid & 31, wid = tid >> 5;
    const int wm = wid & 1, wn = wid >> 1;
    const int bm = blockIdx.y * 128;
    const int half = (blockIdx.x >= nHalfTiles);
    const int bn = (blockIdx.x - half * nHalfTiles) * 128;

    const bf16* Bh = half ? B1h : B0h;
    const bf16* Bl = half ? B1l : B0l;
    const float* bias = half ? b1 : b0;
    __half* C = half ? C1 : C0;

    const int l15 = lane & 15;
    const uint32_t xorq = (uint32_t)(lane & 7) << 4;
    const uint32_t hi16 = (uint32_t)(lane >> 4) * 16;

    uint32_t adst[4], asz[4];
    const bf16* asrc[4];
    uint32_t bdst[4];
    const bf16* bsrc[4];
    #pragma unroll
    for (int i = 0; i < 4; i++) {
        int id = tid + i * 256;
        int arid = id >> 3, aseg = id & 7;
        int apart = aseg >> 2, ac4 = aseg & 3;
        adst[i] = (uint32_t)(arid * 128) +
                  (((uint32_t)(aseg * 16)) ^ ((uint32_t)(arid & 7) << 4));
        int grow = bm + arid;
        asz[i] = (grow < M) ? 16u : 0u;
        asrc[i] = (apart ? Al : Ah) + (size_t)min(grow, M - 1) * K + ac4 * 8;

        int bkrow = id >> 4, bc = id & 15;
        int bpart = bkrow >> 5, bkl = bkrow & 31;
        bdst[i] = 16384u + (uint32_t)(bkrow * 256) +
                  (((uint32_t)(bc * 16)) ^ ((uint32_t)(bkl & 7) << 4));
        bsrc[i] = (bpart ? Bl : Bh) + (size_t)bkl * Nhalf + bn + bc * 8;
    }

    const int nch = K >> 5;
    const size_t aStep = 32;
    const size_t bStep = (size_t)32 * Nhalf;

    #pragma unroll
    for (int s = 0; s < 2; s++) {
        if (s < nch) {
            uint32_t base = sb + s * STG_D;
            #pragma unroll
            for (int i = 0; i < 4; i++)
                cp16(base + adst[i], asrc[i] + (size_t)s * aStep, asz[i]);
            #pragma unroll
            for (int i = 0; i < 4; i++)
                cp16(base + bdst[i], bsrc[i] + (size_t)s * bStep, 16);
        }
        CP_COMMIT();
    }

    float acc[4][4][4];
    #pragma unroll
    for (int mi = 0; mi < 4; mi++)
        #pragma unroll
        for (int ni = 0; ni < 4; ni++)
            #pragma unroll
            for (int r = 0; r < 4; r++) acc[mi][ni][r] = 0.f;

    uint32_t aRowRel[4];
    #pragma unroll
    for (int mi = 0; mi < 4; mi++)
        aRowRel[mi] = (uint32_t)((wm * 64 + mi * 16 + l15) * 128);
    uint32_t bColRel[4];
    #pragma unroll
    for (int ni = 0; ni < 4; ni++)
        bColRel[ni] = ((uint32_t)((wn * 32 + ni * 8) * 2)) ^ xorq;

    for (int kc = 0; kc < nch; kc++) {
        CP_WAIT1();
        __syncthreads();
        int pf = kc + 2;
        if (pf < nch) {
            uint32_t base = sb + (pf % 3) * STG_D;
            #pragma unroll
            for (int i = 0; i < 4; i++)
                cp16(base + adst[i], asrc[i] + (size_t)pf * aStep, asz[i]);
            #pragma unroll
            for (int i = 0; i < 4; i++)
                cp16(base + bdst[i], bsrc[i] + (size_t)pf * bStep, 16);
        }
        CP_COMMIT();

        const uint32_t sA = sb + (kc % 3) * STG_D;
        const uint32_t sB = sA + 16384;

        #pragma unroll
        for (int ks = 0; ks < 2; ks++) {
            uint32_t acolH = ((uint32_t)(ks * 32) + hi16) ^ xorq;
            uint32_t acolL = ((uint32_t)(64 + ks * 32) + hi16) ^ xorq;
            uint32_t browH = sB + (uint32_t)((ks * 16 + l15) * 256);
            uint32_t browL = browH + 32 * 256;

            uint32_t ah[4][4], bh[4][2];
            #pragma unroll
            for (int mi = 0; mi < 4; mi++)
                LDSM_X4(ah[mi], sA + aRowRel[mi] + acolH);
            #pragma unroll
            for (int ni = 0; ni < 4; ni++)
                LDSM_X2T(bh[ni], browH + bColRel[ni]);
            #pragma unroll
            for (int mi = 0; mi < 4; mi++)
                #pragma unroll
                for (int ni = 0; ni < 4; ni++)
                    MMA16816(acc[mi][ni], ah[mi], bh[ni]);
            {
                uint32_t bl[4][2];
                #pragma unroll
                for (int ni = 0; ni < 4; ni++)
                    LDSM_X2T(bl[ni], browL + bColRel[ni]);
                #pragma unroll
                for (int mi = 0; mi < 4; mi++)
                    #pragma unroll
                    for (int ni = 0; ni < 4; ni++)
                        MMA16816(acc[mi][ni], ah[mi], bl[ni]);
            }
            {
                uint32_t al[4][4];
                #pragma unroll
                for (int mi = 0; mi < 4; mi++)
                    LDSM_X4(al[mi], sA + aRowRel[mi] + acolL);
                #pragma unroll
                for (int mi = 0; mi < 4; mi++)
                    #pragma unroll
                    for (int ni = 0; ni < 4; ni++)
                        MMA16816(acc[mi][ni], al[mi], bh[ni]);
            }
        }
    }

    const int row0 = bm + wm * 64 + (lane >> 2);
    const int col0 = bn + wn * 32 + (lane & 3) * 2;
    #pragma unroll
    for (int mi = 0; mi < 4; mi++) {
        #pragma unroll
        for (int h2 = 0; h2 < 2; h2++) {
            int row = row0 + mi * 16 + h2 * 8;
            if (row >= M) continue;
            __half* crow = C + (size_t)row * Nhalf;
            #pragma unroll
            for (int ni = 0; ni < 4; ni++) {
                int col = col0 + ni * 8;
                float2 b = *(const float2*)&bias[col];
                float vx = acc[mi][ni][h2 * 2 + 0] + b.x;
                float vy = acc[mi][ni][h2 * 2 + 1] + b.y;
                *(__half2*)&crow[col] = __floats2half2_rn(vx, vy);
            }
        }
    }
}

// ---------------- JK GEMM over chunk range [cbeg, cbeg+nch) -----------------
#define STG_J   24576
#define GSMEM_J (3 * STG_J)

__global__ __launch_bounds__(256, 2)
void gemm_jk(const bf16* __restrict__ xh,  const bf16* __restrict__ xlo,
             const bf16* __restrict__ h1h, const bf16* __restrict__ h1l,
             const bf16* __restrict__ h2h, const bf16* __restrict__ h2l,
             const bf16* __restrict__ Wh,  const bf16* __restrict__ Wl,
             const float* __restrict__ bias, float* __restrict__ C, int M,
             int cbeg, int nch, int accumulate)
{
    extern __shared__ char sm[];
    const uint32_t sb = smem_u32(sm);
    const int tid = threadIdx.x;
    const int lane = tid & 31, wid = tid >> 5;
    const int wm = wid & 1, wn = wid >> 1;
    const int bm = blockIdx.x * 64;
    const int N = HIDD;

    const int l15 = lane & 15;
    const uint32_t xorq = (uint32_t)(lane & 7) << 4;
    const uint32_t hi16 = (uint32_t)(lane >> 4) * 16;

    int arid[2], apart[2], ac4[2];
    uint32_t adst[2], asz[2];
    int agrow[2];
    #pragma unroll
    for (int i = 0; i < 2; i++) {
        int id = tid + i * 256;
        arid[i] = id >> 3;
        int aseg = id & 7;
        apart[i] = aseg >> 2;
        ac4[i] = aseg & 3;
        adst[i] = (uint32_t)(arid[i] * 128) +
                  (((uint32_t)(aseg * 16)) ^ ((uint32_t)(arid[i] & 7) << 4));
        agrow[i] = min(bm + arid[i], M - 1);
        asz[i] = (bm + arid[i] < M) ? 16u : 0u;
    }
    uint32_t bdst[4];
    int bpart[4], bkl[4], bc[4];
    #pragma unroll
    for (int i = 0; i < 4; i++) {
        int id = tid + i * 256;
        int bkrow = id >> 4;
        bc[i] = id & 15;
        bpart[i] = bkrow >> 5;
        bkl[i] = bkrow & 31;
        bdst[i] = 8192u + (uint32_t)(bkrow * 256) +
                  (((uint32_t)(bc[i] * 16)) ^ ((uint32_t)(bkl[i] & 7) << 4));
    }

    auto issue = [&](int c, uint32_t base) {
        const bf16 *Ah_, *Al_;
        int Kseg, coff;
        if (c < 4)       { Ah_ = xh;  Al_ = xlo; Kseg = HIDD; coff = c; }
        else if (c < 20) { Ah_ = h1h; Al_ = h1l; Kseg = DD1;  coff = c - 4; }
        else             { Ah_ = h2h; Al_ = h2l; Kseg = DD2;  coff = c - 20; }
        #pragma unroll
        for (int i = 0; i < 2; i++) {
            const bf16* src = (apart[i] ? Al_ : Ah_) +
                              (size_t)agrow[i] * Kseg + coff * 32 + ac4[i] * 8;
            cp16(base + adst[i], src, asz[i]);
        }
        #pragma unroll
        for (int i = 0; i < 4; i++) {
            const bf16* src = (bpart[i] ? Wl : Wh) +
                              (size_t)(c * 32 + bkl[i]) * N + bc[i] * 8;
            cp16(base + bdst[i], src, 16);
        }
    };

    #pragma unroll
    for (int s = 0; s < 2; s++) {
        if (s < nch) issue(cbeg + s, sb + s * STG_J);
        CP_COMMIT();
    }

    float acc[2][4][4];
    #pragma unroll
    for (int mi = 0; mi < 2; mi++)
        #pragma unroll
        for (int ni = 0; ni < 4; ni++)
            #pragma unroll
            for (int r = 0; r < 4; r++) acc[mi][ni][r] = 0.f;

    uint32_t aRowRel[2];
    #pragma unroll
    for (int mi = 0; mi < 2; mi++)
        aRowRel[mi] = (uint32_t)((wm * 32 + mi * 16 + l15) * 128);
    uint32_t bColRel[4];
    #pragma unroll
    for (int ni = 0; ni < 4; ni++)
        bColRel[ni] = ((uint32_t)((wn * 32 + ni * 8) * 2)) ^ xorq;

    for (int kc = 0; kc < nch; kc++) {
        CP_WAIT1();
        __syncthreads();
        int pf = kc + 2;
        if (pf < nch) issue(cbeg + pf, sb + (pf % 3) * STG_J);
        CP_COMMIT();

        const uint32_t sA = sb + (kc % 3) * STG_J;
        const uint32_t sB = sA + 8192;

        #pragma unroll
        for (int ks = 0; ks < 2; ks++) {
            uint32_t acolH = ((uint32_t)(ks * 32) + hi16) ^ xorq;
            uint32_t acolL = ((uint32_t)(64 + ks * 32) + hi16) ^ xorq;
            uint32_t browH = sB + (uint32_t)((ks * 16 + l15) * 256);
            uint32_t browL = browH + 32 * 256;

            uint32_t ah[2][4], bh[4][2];
            #pragma unroll
            for (int mi = 0; mi < 2; mi++)
                LDSM_X4(ah[mi], sA + aRowRel[mi] + acolH);
            #pragma unroll
            for (int ni = 0; ni < 4; ni++)
                LDSM_X2T(bh[ni], browH + bColRel[ni]);
            #pragma unroll
            for (int mi = 0; mi < 2; mi++)
                #pragma unroll
                for (int ni = 0; ni < 4; ni++)
                    MMA16816(acc[mi][ni], ah[mi], bh[ni]);
            {
                uint32_t bl[4][2];
                #pragma unroll
                for (int ni = 0; ni < 4; ni++)
                    LDSM_X2T(bl[ni], browL + bColRel[ni]);
                #pragma unroll
                for (int mi = 0; mi < 2; mi++)
                    #pragma unroll
                    for (int ni = 0; ni < 4; ni++)
                        MMA16816(acc[mi][ni], ah[mi], bl[ni]);
            }
            {
                uint32_t al[2][4];
                #pragma unroll
                for (int mi = 0; mi < 2; mi++)
                    LDSM_X4(al[mi], sA + aRowRel[mi] + acolL);
                #pragma unroll
                for (int mi = 0; mi < 2; mi++)
                    #pragma unroll
                    for (int ni = 0; ni < 4; ni++)
                        MMA16816(acc[mi][ni], al[mi], bh[ni]);
            }
        }
    }

    const int row0 = bm + wm * 32 + (lane >> 2);
    const int col0 = wn * 32 + (lane & 3) * 2;
    #pragma unroll
    for (int mi = 0; mi < 2; mi++) {
        #pragma unroll
        for (int half = 0; half < 2; half++) {
            int row = row0 + mi * 16 + half * 8;
            if (row >= M) continue;
            float* crow = C + (size_t)row * N;
            #pragma unroll
            for (int ni = 0; ni < 4; ni++) {
                int col = col0 + ni * 8;
                float2 v;
                v.x = acc[mi][ni][half * 2 + 0];
                v.y = acc[mi][ni][half * 2 + 1];
                if (accumulate) {
                    float2 o = *(float2*)&crow[col];
                    v.x += o.x; v.y += o.y;
                } else {
                    float2 b = *(const float2*)&bias[col];
                    v.x += b.x; v.y += b.y;
                }
                *(float2*)&crow[col] = v;
            }
        }
    }
}

// ---------------- fused GATv2 edge phase: LPH lanes/head, 8 ch/lane ---------
// Depth-2 software prefetch (MLP=3 on the gather stream).
template<int WPN, int LPH>
__global__ __launch_bounds__(256)
void gat_edge_kernel(const __half* __restrict__ xl,
                     const __half* __restrict__ xr,
                     const float* __restrict__ att,
                     const float* __restrict__ bias,
                     bf16* __restrict__ outh,
                     bf16* __restrict__ outl)
{
    constexpr int D   = WPN * 256;
    constexpr int NPB = 8 / WPN;
    const int w    = threadIdx.x >> 5;
    const int lane = threadIdx.x & 31;
    const int node = blockIdx.x * NPB + w / WPN;
    const int sub  = w % WPN;
    const int cbase = sub * 256 + lane * 8;

    float attv[8], xrv[8], acc[8];
    {
        uint4 rx = *(const uint4*)(xr + (size_t)node * D + cbase);
        const __half2* hp = (const __half2*)&rx;
        #pragma unroll
        for (int q = 0; q < 4; q++) {
            float2 f = __half22float2(hp[q]);
            xrv[2 * q] = f.x; xrv[2 * q + 1] = f.y;
        }
        #pragma unroll
        for (int k = 0; k < 8; k++) { attv[k] = att[cbase + k]; acc[k] = 0.f; }
    }

    const int beg = g_rowptr[node], end = g_rowptr[node + 1];
    float s = 0.f;

    uint4 q0, q1, q2;
    q0 = *(const uint4*)(xl + (size_t)g_colsrc[beg] * D + cbase);
    if (beg + 1 < end)
        q1 = *(const uint4*)(xl + (size_t)g_colsrc[beg + 1] * D + cbase);
    for (int j = beg; j < end; j++) {
        if (j + 2 < end)
            q2 = *(const uint4*)(xl + (size_t)g_colsrc[j + 2] * D + cbase);
        float x[8];
        {
            const __half2* hp = (const __half2*)&q0;
            #pragma unroll
            for (int q = 0; q < 4; q++) {
                float2 f = __half22float2(hp[q]);
                x[2 * q] = f.x; x[2 * q + 1] = f.y;
            }
        }
        float e = 0.f;
        #pragma unroll
        for (int k = 0; k < 8; k++) {
            float t = x[k] + xrv[k];
            t = fmaxf(t, 0.2f * t);
            e = fmaf(t, attv[k], e);
        }
        #pragma unroll
        for (int o = 1; o < LPH; o <<= 1)
            e += __shfl_xor_sync(0xffffffffu, e, o);
        float wgt = __expf(e);
        s += wgt;
        #pragma unroll
        for (int k = 0; k < 8; k++)
            acc[k] = fmaf(wgt, x[k], acc[k]);
        q0 = q1;
        q1 = q2;
    }

    float inv = 1.0f / s;
    bf16 oh[8], ol[8];
    #pragma unroll
    for (int k = 0; k < 8; k++) {
        float v = acc[k] * inv + bias[cbase + k];
        v = (v > 0.f) ? v : expm1f(v);
        oh[k] = __float2bfloat16_rn(v);
        ol[k] = __float2bfloat16_rn(v - __bfloat162float(oh[k]));
    }
    *(uint4*)(outh + (size_t)node * D + cbase) = *(uint4*)oh;
    *(uint4*)(outl + (size_t)node * D + cbase) = *(uint4*)ol;
}

// ---------------- launch ----------------------------------------------------
extern "C" void kernel_launch(void* const* d_in, const int* in_sizes, int n_in,
                              void* d_out, int out_size)
{
    const float* x     = (const float*)d_in[0];
    const int*   ei    = (const int*)  d_in[1];
    const float* Wl1   = (const float*)d_in[2];
    const float* bl1   = (const float*)d_in[3];
    const float* Wr1   = (const float*)d_in[4];
    const float* br1   = (const float*)d_in[5];
    const float* att1  = (const float*)d_in[6];
    const float* bias1 = (const float*)d_in[7];
    const float* Wl2   = (const float*)d_in[8];
    const float* bl2   = (const float*)d_in[9];
    const float* Wr2   = (const float*)d_in[10];
    const float* br2   = (const float*)d_in[11];
    const float* att2  = (const float*)d_in[12];
    const float* bias2 = (const float*)d_in[13];
    const float* Wjk   = (const float*)d_in[14];
    const float* bjk   = (const float*)d_in[15];
    float* out = (float*)d_out;

    __half *xl1, *xr1, *xl2, *xr2;
    bf16 *xh, *xlo, *h1h, *h1l, *h2h, *h2l;
    bf16 *Wl1h, *Wl1l, *Wr1h, *Wr1l, *Wl2h, *Wl2l, *Wr2h, *Wr2l, *Wjkh, *Wjkl;
    cudaGetSymbolAddress((void**)&xl1,  g_xl1);
    cudaGetSymbolAddress((void**)&xr1,  g_xr1);
    cudaGetSymbolAddress((void**)&xl2,  g_xl2);
    cudaGetSymbolAddress((void**)&xr2,  g_xr2);
    cudaGetSymbolAddress((void**)&xh,   g_xh);
    cudaGetSymbolAddress((void**)&xlo,  g_xlo);
    cudaGetSymbolAddress((void**)&h1h,  g_h1h);
    cudaGetSymbolAddress((void**)&h1l,  g_h1l);
    cudaGetSymbolAddress((void**)&h2h,  g_h2h);
    cudaGetSymbolAddress((void**)&h2l,  g_h2l);
    cudaGetSymbolAddress((void**)&Wl1h, g_Wl1h);
    cudaGetSymbolAddress((void**)&Wl1l, g_Wl1l);
    cudaGetSymbolAddress((void**)&Wr1h, g_Wr1h);
    cudaGetSymbolAddress((void**)&Wr1l, g_Wr1l);
    cudaGetSymbolAddress((void**)&Wl2h, g_Wl2h);
    cudaGetSymbolAddress((void**)&Wl2l, g_Wl2l);
    cudaGetSymbolAddress((void**)&Wr2h, g_Wr2h);
    cudaGetSymbolAddress((void**)&Wr2l, g_Wr2l);
    cudaGetSymbolAddress((void**)&Wjkh, g_Wjkh);
    cudaGetSymbolAddress((void**)&Wjkl, g_Wjkl);

    cudaFuncSetAttribute(gemm_dual, cudaFuncAttributeMaxDynamicSharedMemorySize,
                         GSMEM_D);
    cudaFuncSetAttribute(gemm_jk, cudaFuncAttributeMaxDynamicSharedMemorySize,
                         GSMEM_J);

    cudaStream_t s1;
    cudaStreamCreateWithFlags(&s1, cudaStreamNonBlocking);
    cudaEvent_t eStart, eCvtX, eCsr, eEdge1, eJKa;
    cudaEventCreateWithFlags(&eStart, cudaEventDisableTiming);
    cudaEventCreateWithFlags(&eCvtX,  cudaEventDisableTiming);
    cudaEventCreateWithFlags(&eCsr,   cudaEventDisableTiming);
    cudaEventCreateWithFlags(&eEdge1, cudaEventDisableTiming);
    cudaEventCreateWithFlags(&eJKa,   cudaEventDisableTiming);

    const int MT = (NN + 127) / 128;
    const int JT = (NN + 63) / 64;

    // fork
    cudaEventRecord(eStart, 0);
    cudaStreamWaitEvent(s1, eStart, 0);

    // side stream: W2/Wjk conversions + CSR build
    {
        CvtJobs jobs;
        jobs.s[0] = Wl2; jobs.h[0] = Wl2h; jobs.l[0] = Wl2l; jobs.n[0] = DD1 * DD2;
        jobs.s[1] = Wr2; jobs.h[1] = Wr2h; jobs.l[1] = Wr2l; jobs.n[1] = DD1 * DD2;
        jobs.s[2] = Wjk; jobs.h[2] = Wjkh; jobs.l[2] = Wjkl; jobs.n[2] = 896 * HIDD;
        int gx = (DD1 * DD2 / 4 + 255) / 256;
        cvt_kernel<<<dim3(gx, 3), 256, 0, s1>>>(jobs);
    }
    init_hist_kernel<<<(NN + 255) / 256, 256, 0, s1>>>();
    hist_kernel<<<(EE + 255) / 256, 256, 0, s1>>>(ei);
    scan_kernel<<<1, 1024, 0, s1>>>();
    scatter_kernel<<<(ETOT + 255) / 256, 256, 0, s1>>>(ei);
    cudaEventRecord(eCsr, s1);

    // main stream: x + W1 conversions, then layer-1 GEMM
    {
        CvtJobs jobs;
        jobs.s[0] = x;   jobs.h[0] = xh;   jobs.l[0] = xlo;  jobs.n[0] = NN * HIDD;
        jobs.s[1] = Wl1; jobs.h[1] = Wl1h; jobs.l[1] = Wl1l; jobs.n[1] = HIDD * DD1;
        jobs.s[2] = Wr1; jobs.h[2] = Wr1h; jobs.l[2] = Wr1l; jobs.n[2] = HIDD * DD1;
        int gx = (NN * HIDD / 4 + 255) / 256;
        cvt_kernel<<<dim3(gx, 3), 256>>>(jobs);
    }
    cudaEventRecord(eCvtX, 0);
    gemm_dual<<<dim3(8, MT), 256, GSMEM_D>>>(
        xh, xlo, Wl1h, Wl1l, Wr1h, Wr1l, bl1, br1, xl1, xr1,
        NN, HIDD, DD1, 4);

    // side stream: JK_x (chunks 0..3, writes out+bias) under gemm L1's window
    cudaStreamWaitEvent(s1, eCvtX, 0);
    gemm_jk<<<JT, 256, GSMEM_J, s1>>>(
        xh, xlo, h1h, h1l, h2h, h2l, Wjkh, Wjkl, bjk, out, NN, 0, 4, 0);

    // main: edge layer 1 (after CSR join)
    cudaStreamWaitEvent(0, eCsr, 0);
    gat_edge_kernel<2, 8><<<NN / 4, 256>>>(xl1, xr1, att1, bias1, h1h, h1l);
    cudaEventRecord(eEdge1, 0);

    // side stream: JK_h1 (chunks 4..19, accumulate) overlaps L2 phase
    cudaStreamWaitEvent(s1, eEdge1, 0);
    gemm_jk<<<JT, 256, GSMEM_J, s1>>>(
        xh, xlo, h1h, h1l, h2h, h2l, Wjkh, Wjkl, bjk, out, NN, 4, 16, 1);
    cudaEventRecord(eJKa, s1);

    // main stream: layer-2 GEMM + edge layer 2
    gemm_dual<<<dim3(4, MT), 256, GSMEM_D>>>(
        h1h, h1l, Wl2h, Wl2l, Wr2h, Wr2l, bl2, br2, xl2, xr2,
        NN, DD1, DD2, 2);
    gat_edge_kernel<1, 4><<<NN / 8, 256>>>(xl2, xr2, att2, bias2, h2h, h2l);

    // join JK_h1, then JK_h2 (chunks 20..27, accumulate)
    cudaStreamWaitEvent(0, eJKa, 0);
    gemm_jk<<<JT, 256, GSMEM_J>>>(
        xh, xlo, h1h, h1l, h2h, h2l, Wjkh, Wjkl, bjk, out, NN, 20, 8, 1);

    cudaEventDestroy(eStart);
    cudaEventDestroy(eCvtX);
    cudaEventDestroy(eCsr);
    cudaEventDestroy(eEdge1);
    cudaEventDestroy(eJKa);
    cudaStreamDestroy(s1);
}

// round 16
// speedup vs baseline: 1.0419x; 1.0419x over previous
#include <cuda_runtime.h>
#include <cuda_bf16.h>
#include <cuda_fp16.h>
#include <math.h>
#include <stdint.h>

#define NN   20000
#define EE   320000
#define ETOT (EE + NN)
#define HIDD 128
#define DD1  512
#define DD2  256

typedef __nv_bfloat16 bf16;

// ---------------- device scratch --------------------------------------------
__device__ __half g_xl1[(size_t)NN * DD1];
__device__ __half g_xr1[(size_t)NN * DD1];
__device__ __half g_xl2[(size_t)NN * DD2];
__device__ __half g_xr2[(size_t)NN * DD2];
__device__ bf16  g_xh [(size_t)NN * HIDD];
__device__ bf16  g_xlo[(size_t)NN * HIDD];
__device__ bf16  g_h1h[(size_t)NN * DD1];
__device__ bf16  g_h1l[(size_t)NN * DD1];
__device__ bf16  g_h2h[(size_t)NN * DD2];
__device__ bf16  g_h2l[(size_t)NN * DD2];
__device__ bf16  g_Wl1h[HIDD * DD1], g_Wl1l[HIDD * DD1];
__device__ bf16  g_Wr1h[HIDD * DD1], g_Wr1l[HIDD * DD1];
__device__ bf16  g_Wl2h[DD1 * DD2],  g_Wl2l[DD1 * DD2];
__device__ bf16  g_Wr2h[DD1 * DD2],  g_Wr2l[DD1 * DD2];
__device__ bf16  g_Wjkh[896 * HIDD], g_Wjkl[896 * HIDD];
__device__ int   g_rowptr[NN + 1];
__device__ int   g_cursor[NN];
__device__ int   g_colsrc[ETOT];

// ---------------- CSR build -------------------------------------------------
__global__ void init_hist_kernel() {
    int i = blockIdx.x * blockDim.x + threadIdx.x;
    if (i < NN) g_cursor[i] = 1;   // self loop per node
}

__global__ void hist_kernel(const int* __restrict__ ei) {
    int e = blockIdx.x * blockDim.x + threadIdx.x;
    if (e < EE) atomicAdd(&g_cursor[ei[EE + e]], 1);
}

__global__ void scan_kernel() {
    const int PER = 20;
    __shared__ int sh[1024];
    int t = threadIdx.x;
    int base = t * PER;
    int loc[PER];
    int sum = 0;
    #pragma unroll
    for (int i = 0; i < PER; i++) {
        int idx = base + i;
        int v = (idx < NN) ? g_cursor[idx] : 0;
        loc[i] = v;
        sum += v;
    }
    sh[t] = sum;
    __syncthreads();
    #pragma unroll
    for (int off = 1; off < 1024; off <<= 1) {
        int v = (t >= off) ? sh[t - off] : 0;
        __syncthreads();
        sh[t] += v;
        __syncthreads();
    }
    int run = sh[t] - sum;
    #pragma unroll
    for (int i = 0; i < PER; i++) {
        int idx = base + i;
        if (idx < NN) { g_rowptr[idx] = run; g_cursor[idx] = run; }
        run += loc[i];
    }
    if (t == 1023) g_rowptr[NN] = sh[1023];
}

__global__ void scatter_kernel(const int* __restrict__ ei) {
    int t = blockIdx.x * blockDim.x + threadIdx.x;
    if (t < EE) {
        int s = ei[t];
        int d = ei[EE + t];
        int pos = atomicAdd(&g_cursor[d], 1);
        g_colsrc[pos] = s;
    } else if (t < ETOT) {
        int i = t - EE;
        int pos = atomicAdd(&g_cursor[i], 1);
        g_colsrc[pos] = i;
    }
}

// ---------------- fp32 -> bf16 hi/lo split, all sources in one launch -------
struct CvtJobs {
    const float* s[6];
    bf16* h[6];
    bf16* l[6];
    int   n[6];
};

__global__ void cvt_all_kernel(CvtJobs jobs) {
    int y = blockIdx.y;
    int n = jobs.n[y];
    int i = (blockIdx.x * blockDim.x + threadIdx.x) * 4;
    if (i >= n) return;
    const float* s = jobs.s[y];
    float4 v = *(const float4*)(s + i);
    bf16 hh[4], ll[4];
    hh[0] = __float2bfloat16_rn(v.x);
    hh[1] = __float2bfloat16_rn(v.y);
    hh[2] = __float2bfloat16_rn(v.z);
    hh[3] = __float2bfloat16_rn(v.w);
    ll[0] = __float2bfloat16_rn(v.x - __bfloat162float(hh[0]));
    ll[1] = __float2bfloat16_rn(v.y - __bfloat162float(hh[1]));
    ll[2] = __float2bfloat16_rn(v.z - __bfloat162float(hh[2]));
    ll[3] = __float2bfloat16_rn(v.w - __bfloat162float(hh[3]));
    *(uint2*)(jobs.h[y] + i) = *(uint2*)hh;
    *(uint2*)(jobs.l[y] + i) = *(uint2*)ll;
}

// ---------------- shared GEMM plumbing ---------------------------------------
__device__ __forceinline__ uint32_t smem_u32(const void* p) {
    return (uint32_t)__cvta_generic_to_shared(p);
}

__device__ __forceinline__ void cp16(uint32_t dst, const void* src, uint32_t sz) {
    asm volatile("cp.async.cg.shared.global [%0], [%1], 16, %2;"
                 :: "r"(dst), "l"(src), "r"(sz) : "memory");
}
#define CP_COMMIT() asm volatile("cp.async.commit_group;" ::: "memory")
#define CP_WAIT1()  asm volatile("cp.async.wait_group 1;" ::: "memory")

#define LDSM_X4(r, addr) \
    asm volatile("ldmatrix.sync.aligned.m8n8.x4.shared.b16 {%0,%1,%2,%3}, [%4];" \
        : "=r"((r)[0]), "=r"((r)[1]), "=r"((r)[2]), "=r"((r)[3]) : "r"(addr))

#define LDSM_X2T(r, addr) \
    asm volatile("ldmatrix.sync.aligned.m8n8.x2.trans.shared.b16 {%0,%1}, [%2];" \
        : "=r"((r)[0]), "=r"((r)[1]) : "r"(addr))

#define MMA16816(d, a, b) \
    asm volatile("mma.sync.aligned.m16n8k16.row.col.f32.bf16.bf16.f32 " \
        "{%0,%1,%2,%3},{%4,%5,%6,%7},{%8,%9},{%0,%1,%2,%3};" \
        : "+f"((d)[0]), "+f"((d)[1]), "+f"((d)[2]), "+f"((d)[3]) \
        : "r"((a)[0]), "r"((a)[1]), "r"((a)[2]), "r"((a)[3]), \
          "r"((b)[0]), "r"((b)[1]))

// ---------------- dual-output bf16 GEMM (3-term split), fp16 out ------------
#define STG_D   32768
#define GSMEM_D (3 * STG_D)

__global__ __launch_bounds__(256, 2)
void gemm_dual(const bf16* __restrict__ Ah, const bf16* __restrict__ Al,
               const bf16* __restrict__ B0h, const bf16* __restrict__ B0l,
               const bf16* __restrict__ B1h, const bf16* __restrict__ B1l,
               const float* __restrict__ b0, const float* __restrict__ b1,
               __half* __restrict__ C0, __half* __restrict__ C1,
               int M, int K, int Nhalf, int nHalfTiles)
{
    extern __shared__ char sm[];
    const uint32_t sb = smem_u32(sm);
    const int tid = threadIdx.x;
    const int lane = tid & 31, wid = tid >> 5;
    const int wm = wid & 1, wn = wid >> 1;
    const int bm = blockIdx.y * 128;
    const int half = (blockIdx.x >= nHalfTiles);
    const int bn = (blockIdx.x - half * nHalfTiles) * 128;

    const bf16* Bh = half ? B1h : B0h;
    const bf16* Bl = half ? B1l : B0l;
    const float* bias = half ? b1 : b0;
    __half* C = half ? C1 : C0;

    const int l15 = lane & 15;
    const uint32_t xorq = (uint32_t)(lane & 7) << 4;
    const uint32_t hi16 = (uint32_t)(lane >> 4) * 16;

    uint32_t adst[4], asz[4];
    const bf16* asrc[4];
    uint32_t bdst[4];
    const bf16* bsrc[4];
    #pragma unroll
    for (int i = 0; i < 4; i++) {
        int id = tid + i * 256;
        int arid = id >> 3, aseg = id & 7;
        int apart = aseg >> 2, ac4 = aseg & 3;
        adst[i] = (uint32_t)(arid * 128) +
                  (((uint32_t)(aseg * 16)) ^ ((uint32_t)(arid & 7) << 4));
        int grow = bm + arid;
        asz[i] = (grow < M) ? 16u : 0u;
        asrc[i] = (apart ? Al : Ah) + (size_t)min(grow, M - 1) * K + ac4 * 8;

        int bkrow = id >> 4, bc = id & 15;
        int bpart = bkrow >> 5, bkl = bkrow & 31;
        bdst[i] = 16384u + (uint32_t)(bkrow * 256) +
                  (((uint32_t)(bc * 16)) ^ ((uint32_t)(bkl & 7) << 4));
        bsrc[i] = (bpart ? Bl : Bh) + (size_t)bkl * Nhalf + bn + bc * 8;
    }

    const int nch = K >> 5;
    const size_t aStep = 32;
    const size_t bStep = (size_t)32 * Nhalf;

    #pragma unroll
    for (int s = 0; s < 2; s++) {
        if (s < nch) {
            uint32_t base = sb + s * STG_D;
            #pragma unroll
            for (int i = 0; i < 4; i++)
                cp16(base + adst[i], asrc[i] + (size_t)s * aStep, asz[i]);
            #pragma unroll
            for (int i = 0; i < 4; i++)
                cp16(base + bdst[i], bsrc[i] + (size_t)s * bStep, 16);
        }
        CP_COMMIT();
    }

    float acc[4][4][4];
    #pragma unroll
    for (int mi = 0; mi < 4; mi++)
        #pragma unroll
        for (int ni = 0; ni < 4; ni++)
            #pragma unroll
            for (int r = 0; r < 4; r++) acc[mi][ni][r] = 0.f;

    uint32_t aRowRel[4];
    #pragma unroll
    for (int mi = 0; mi < 4; mi++)
        aRowRel[mi] = (uint32_t)((wm * 64 + mi * 16 + l15) * 128);
    uint32_t bColRel[4];
    #pragma unroll
    for (int ni = 0; ni < 4; ni++)
        bColRel[ni] = ((uint32_t)((wn * 32 + ni * 8) * 2)) ^ xorq;

    for (int kc = 0; kc < nch; kc++) {
        CP_WAIT1();
        __syncthreads();
        int pf = kc + 2;
        if (pf < nch) {
            uint32_t base = sb + (pf % 3) * STG_D;
            #pragma unroll
            for (int i = 0; i < 4; i++)
                cp16(base + adst[i], asrc[i] + (size_t)pf * aStep, asz[i]);
            #pragma unroll
            for (int i = 0; i < 4; i++)
                cp16(base + bdst[i], bsrc[i] + (size_t)pf * bStep, 16);
        }
        CP_COMMIT();

        const uint32_t sA = sb + (kc % 3) * STG_D;
        const uint32_t sB = sA + 16384;

        #pragma unroll
        for (int ks = 0; ks < 2; ks++) {
            uint32_t acolH = ((uint32_t)(ks * 32) + hi16) ^ xorq;
            uint32_t acolL = ((uint32_t)(64 + ks * 32) + hi16) ^ xorq;
            uint32_t browH = sB + (uint32_t)((ks * 16 + l15) * 256);
            uint32_t browL = browH + 32 * 256;

            uint32_t ah[4][4], bh[4][2];
            #pragma unroll
            for (int mi = 0; mi < 4; mi++)
                LDSM_X4(ah[mi], sA + aRowRel[mi] + acolH);
            #pragma unroll
            for (int ni = 0; ni < 4; ni++)
                LDSM_X2T(bh[ni], browH + bColRel[ni]);
            #pragma unroll
            for (int mi = 0; mi < 4; mi++)
                #pragma unroll
                for (int ni = 0; ni < 4; ni++)
                    MMA16816(acc[mi][ni], ah[mi], bh[ni]);
            {
                uint32_t bl[4][2];
                #pragma unroll
                for (int ni = 0; ni < 4; ni++)
                    LDSM_X2T(bl[ni], browL + bColRel[ni]);
                #pragma unroll
                for (int mi = 0; mi < 4; mi++)
                    #pragma unroll
                    for (int ni = 0; ni < 4; ni++)
                        MMA16816(acc[mi][ni], ah[mi], bl[ni]);
            }
            {
                uint32_t al[4][4];
                #pragma unroll
                for (int mi = 0; mi < 4; mi++)
                    LDSM_X4(al[mi], sA + aRowRel[mi] + acolL);
                #pragma unroll
                for (int mi = 0; mi < 4; mi++)
                    #pragma unroll
                    for (int ni = 0; ni < 4; ni++)
                        MMA16816(acc[mi][ni], al[mi], bh[ni]);
            }
        }
    }

    const int row0 = bm + wm * 64 + (lane >> 2);
    const int col0 = bn + wn * 32 + (lane & 3) * 2;
    #pragma unroll
    for (int mi = 0; mi < 4; mi++) {
        #pragma unroll
        for (int h2 = 0; h2 < 2; h2++) {
            int row = row0 + mi * 16 + h2 * 8;
            if (row >= M) continue;
            __half* crow = C + (size_t)row * Nhalf;
            #pragma unroll
            for (int ni = 0; ni < 4; ni++) {
                int col = col0 + ni * 8;
                float2 b = *(const float2*)&bias[col];
                float vx = acc[mi][ni][h2 * 2 + 0] + b.x;
                float vy = acc[mi][ni][h2 * 2 + 1] + b.y;
                *(__half2*)&crow[col] = __floats2half2_rn(vx, vy);
            }
        }
    }
}

// ---------------- JK GEMM over chunk range [cbeg, cbeg+nch) -----------------
#define STG_J   24576
#define GSMEM_J (3 * STG_J)

__global__ __launch_bounds__(256, 2)
void gemm_jk(const bf16* __restrict__ xh,  const bf16* __restrict__ xlo,
             const bf16* __restrict__ h1h, const bf16* __restrict__ h1l,
             const bf16* __restrict__ h2h, const bf16* __restrict__ h2l,
             const bf16* __restrict__ Wh,  const bf16* __restrict__ Wl,
             const float* __restrict__ bias, float* __restrict__ C, int M,
             int cbeg, int nch, int accumulate)
{
    extern __shared__ char sm[];
    const uint32_t sb = smem_u32(sm);
    const int tid = threadIdx.x;
    const int lane = tid & 31, wid = tid >> 5;
    const int wm = wid & 1, wn = wid >> 1;
    const int bm = blockIdx.x * 64;
    const int N = HIDD;

    const int l15 = lane & 15;
    const uint32_t xorq = (uint32_t)(lane & 7) << 4;
    const uint32_t hi16 = (uint32_t)(lane >> 4) * 16;

    int arid[2], apart[2], ac4[2];
    uint32_t adst[2], asz[2];
    int agrow[2];
    #pragma unroll
    for (int i = 0; i < 2; i++) {
        int id = tid + i * 256;
        arid[i] = id >> 3;
        int aseg = id & 7;
        apart[i] = aseg >> 2;
        ac4[i] = aseg & 3;
        adst[i] = (uint32_t)(arid[i] * 128) +
                  (((uint32_t)(aseg * 16)) ^ ((uint32_t)(arid[i] & 7) << 4));
        agrow[i] = min(bm + arid[i], M - 1);
        asz[i] = (bm + arid[i] < M) ? 16u : 0u;
    }
    uint32_t bdst[4];
    int bpart[4], bkl[4], bc[4];
    #pragma unroll
    for (int i = 0; i < 4; i++) {
        int id = tid + i * 256;
        int bkrow = id >> 4;
        bc[i] = id & 15;
        bpart[i] = bkrow >> 5;
        bkl[i] = bkrow & 31;
        bdst[i] = 8192u + (uint32_t)(bkrow * 256) +
                  (((uint32_t)(bc[i] * 16)) ^ ((uint32_t)(bkl[i] & 7) << 4));
    }

    auto issue = [&](int c, uint32_t base) {
        const bf16 *Ah_, *Al_;
        int Kseg, coff;
        if (c < 4)       { Ah_ = xh;  Al_ = xlo; Kseg = HIDD; coff = c; }
        else if (c < 20) { Ah_ = h1h; Al_ = h1l; Kseg = DD1;  coff = c - 4; }
        else             { Ah_ = h2h; Al_ = h2l; Kseg = DD2;  coff = c - 20; }
        #pragma unroll
        for (int i = 0; i < 2; i++) {
            const bf16* src = (apart[i] ? Al_ : Ah_) +
                              (size_t)agrow[i] * Kseg + coff * 32 + ac4[i] * 8;
            cp16(base + adst[i], src, asz[i]);
        }
        #pragma unroll
        for (int i = 0; i < 4; i++) {
            const bf16* src = (bpart[i] ? Wl : Wh) +
                              (size_t)(c * 32 + bkl[i]) * N + bc[i] * 8;
            cp16(base + bdst[i], src, 16);
        }
    };

    #pragma unroll
    for (int s = 0; s < 2; s++) {
        if (s < nch) issue(cbeg + s, sb + s * STG_J);
        CP_COMMIT();
    }

    float acc[2][4][4];
    #pragma unroll
    for (int mi = 0; mi < 2; mi++)
        #pragma unroll
        for (int ni = 0; ni < 4; ni++)
            #pragma unroll
            for (int r = 0; r < 4; r++) acc[mi][ni][r] = 0.f;

    uint32_t aRowRel[2];
    #pragma unroll
    for (int mi = 0; mi < 2; mi++)
        aRowRel[mi] = (uint32_t)((wm * 32 + mi * 16 + l15) * 128);
    uint32_t bColRel[4];
    #pragma unroll
    for (int ni = 0; ni < 4; ni++)
        bColRel[ni] = ((uint32_t)((wn * 32 + ni * 8) * 2)) ^ xorq;

    for (int kc = 0; kc < nch; kc++) {
        CP_WAIT1();
        __syncthreads();
        int pf = kc + 2;
        if (pf < nch) issue(cbeg + pf, sb + (pf % 3) * STG_J);
        CP_COMMIT();

        const uint32_t sA = sb + (kc % 3) * STG_J;
        const uint32_t sB = sA + 8192;

        #pragma unroll
        for (int ks = 0; ks < 2; ks++) {
            uint32_t acolH = ((uint32_t)(ks * 32) + hi16) ^ xorq;
            uint32_t acolL = ((uint32_t)(64 + ks * 32) + hi16) ^ xorq;
            uint32_t browH = sB + (uint32_t)((ks * 16 + l15) * 256);
            uint32_t browL = browH + 32 * 256;

            uint32_t ah[2][4], bh[4][2];
            #pragma unroll
            for (int mi = 0; mi < 2; mi++)
                LDSM_X4(ah[mi], sA + aRowRel[mi] + acolH);
            #pragma unroll
            for (int ni = 0; ni < 4; ni++)
                LDSM_X2T(bh[ni], browH + bColRel[ni]);
            #pragma unroll
            for (int mi = 0; mi < 2; mi++)
                #pragma unroll
                for (int ni = 0; ni < 4; ni++)
                    MMA16816(acc[mi][ni], ah[mi], bh[ni]);
            {
                uint32_t bl[4][2];
                #pragma unroll
                for (int ni = 0; ni < 4; ni++)
                    LDSM_X2T(bl[ni], browL + bColRel[ni]);
                #pragma unroll
                for (int mi = 0; mi < 2; mi++)
                    #pragma unroll
                    for (int ni = 0; ni < 4; ni++)
                        MMA16816(acc[mi][ni], ah[mi], bl[ni]);
            }
            {
                uint32_t al[2][4];
                #pragma unroll
                for (int mi = 0; mi < 2; mi++)
                    LDSM_X4(al[mi], sA + aRowRel[mi] + acolL);
                #pragma unroll
                for (int mi = 0; mi < 2; mi++)
                    #pragma unroll
                    for (int ni = 0; ni < 4; ni++)
                        MMA16816(acc[mi][ni], al[mi], bh[ni]);
            }
        }
    }

    const int row0 = bm + wm * 32 + (lane >> 2);
    const int col0 = wn * 32 + (lane & 3) * 2;
    #pragma unroll
    for (int mi = 0; mi < 2; mi++) {
        #pragma unroll
        for (int half = 0; half < 2; half++) {
            int row = row0 + mi * 16 + half * 8;
            if (row >= M) continue;
            float* crow = C + (size_t)row * N;
            #pragma unroll
            for (int ni = 0; ni < 4; ni++) {
                int col = col0 + ni * 8;
                float2 v;
                v.x = acc[mi][ni][half * 2 + 0];
                v.y = acc[mi][ni][half * 2 + 1];
                if (accumulate) {
                    float2 o = *(float2*)&crow[col];
                    v.x += o.x; v.y += o.y;
                } else {
                    float2 b = *(const float2*)&bias[col];
                    v.x += b.x; v.y += b.y;
                }
                *(float2*)&crow[col] = v;
            }
        }
    }
}

// ---------------- fused GATv2 edge phase: LPH lanes/head, 8 ch/lane ---------
// (R14-proven depth-1 prefetch version)
template<int WPN, int LPH>
__global__ __launch_bounds__(256)
void gat_edge_kernel(const __half* __restrict__ xl,
                     const __half* __restrict__ xr,
                     const float* __restrict__ att,
                     const float* __restrict__ bias,
                     bf16* __restrict__ outh,
                     bf16* __restrict__ outl)
{
    constexpr int D   = WPN * 256;
    constexpr int NPB = 8 / WPN;
    const int w    = threadIdx.x >> 5;
    const int lane = threadIdx.x & 31;
    const int node = blockIdx.x * NPB + w / WPN;
    const int sub  = w % WPN;
    const int cbase = sub * 256 + lane * 8;

    float attv[8], xrv[8], acc[8];
    {
        uint4 rx = *(const uint4*)(xr + (size_t)node * D + cbase);
        const __half2* hp = (const __half2*)&rx;
        #pragma unroll
        for (int q = 0; q < 4; q++) {
            float2 f = __half22float2(hp[q]);
            xrv[2 * q] = f.x; xrv[2 * q + 1] = f.y;
        }
        #pragma unroll
        for (int k = 0; k < 8; k++) { attv[k] = att[cbase + k]; acc[k] = 0.f; }
    }

    const int beg = g_rowptr[node], end = g_rowptr[node + 1];
    float s = 0.f;

    uint4 cur, nxt;
    cur = *(const uint4*)(xl + (size_t)g_colsrc[beg] * D + cbase);
    for (int j = beg; j < end; j++) {
        if (j + 1 < end)
            nxt = *(const uint4*)(xl + (size_t)g_colsrc[j + 1] * D + cbase);
        float x[8];
        {
            const __half2* hp = (const __half2*)&cur;
            #pragma unroll
            for (int q = 0; q < 4; q++) {
                float2 f = __half22float2(hp[q]);
                x[2 * q] = f.x; x[2 * q + 1] = f.y;
            }
        }
        float e = 0.f;
        #pragma unroll
        for (int k = 0; k < 8; k++) {
            float t = x[k] + xrv[k];
            t = fmaxf(t, 0.2f * t);          // leaky_relu(0.2), exact
            e = fmaf(t, attv[k], e);
        }
        #pragma unroll
        for (int o = 1; o < LPH; o <<= 1)    // head logit (LPH-lane group)
            e += __shfl_xor_sync(0xffffffffu, e, o);
        float wgt = __expf(e);
        s += wgt;
        #pragma unroll
        for (int k = 0; k < 8; k++)
            acc[k] = fmaf(wgt, x[k], acc[k]);
        cur = nxt;
    }

    float inv = 1.0f / s;
    bf16 oh[8], ol[8];
    #pragma unroll
    for (int k = 0; k < 8; k++) {
        float v = acc[k] * inv + bias[cbase + k];
        v = (v > 0.f) ? v : expm1f(v);       // elu
        oh[k] = __float2bfloat16_rn(v);
        ol[k] = __float2bfloat16_rn(v - __bfloat162float(oh[k]));
    }
    *(uint4*)(outh + (size_t)node * D + cbase) = *(uint4*)oh;
    *(uint4*)(outl + (size_t)node * D + cbase) = *(uint4*)ol;
}

// ---------------- launch ----------------------------------------------------
extern "C" void kernel_launch(void* const* d_in, const int* in_sizes, int n_in,
                              void* d_out, int out_size)
{
    const float* x     = (const float*)d_in[0];
    const int*   ei    = (const int*)  d_in[1];
    const float* Wl1   = (const float*)d_in[2];
    const float* bl1   = (const float*)d_in[3];
    const float* Wr1   = (const float*)d_in[4];
    const float* br1   = (const float*)d_in[5];
    const float* att1  = (const float*)d_in[6];
    const float* bias1 = (const float*)d_in[7];
    const float* Wl2   = (const float*)d_in[8];
    const float* bl2   = (const float*)d_in[9];
    const float* Wr2   = (const float*)d_in[10];
    const float* br2   = (const float*)d_in[11];
    const float* att2  = (const float*)d_in[12];
    const float* bias2 = (const float*)d_in[13];
    const float* Wjk   = (const float*)d_in[14];
    const float* bjk   = (const float*)d_in[15];
    float* out = (float*)d_out;

    __half *xl1, *xr1, *xl2, *xr2;
    bf16 *xh, *xlo, *h1h, *h1l, *h2h, *h2l;
    bf16 *Wl1h, *Wl1l, *Wr1h, *Wr1l, *Wl2h, *Wl2l, *Wr2h, *Wr2l, *Wjkh, *Wjkl;
    cudaGetSymbolAddress((void**)&xl1,  g_xl1);
    cudaGetSymbolAddress((void**)&xr1,  g_xr1);
    cudaGetSymbolAddress((void**)&xl2,  g_xl2);
    cudaGetSymbolAddress((void**)&xr2,  g_xr2);
    cudaGetSymbolAddress((void**)&xh,   g_xh);
    cudaGetSymbolAddress((void**)&xlo,  g_xlo);
    cudaGetSymbolAddress((void**)&h1h,  g_h1h);
    cudaGetSymbolAddress((void**)&h1l,  g_h1l);
    cudaGetSymbolAddress((void**)&h2h,  g_h2h);
    cudaGetSymbolAddress((void**)&h2l,  g_h2l);
    cudaGetSymbolAddress((void**)&Wl1h, g_Wl1h);
    cudaGetSymbolAddress((void**)&Wl1l, g_Wl1l);
    cudaGetSymbolAddress((void**)&Wr1h, g_Wr1h);
    cudaGetSymbolAddress((void**)&Wr1l, g_Wr1l);
    cudaGetSymbolAddress((void**)&Wl2h, g_Wl2h);
    cudaGetSymbolAddress((void**)&Wl2l, g_Wl2l);
    cudaGetSymbolAddress((void**)&Wr2h, g_Wr2h);
    cudaGetSymbolAddress((void**)&Wr2l, g_Wr2l);
    cudaGetSymbolAddress((void**)&Wjkh, g_Wjkh);
    cudaGetSymbolAddress((void**)&Wjkl, g_Wjkl);

    cudaFuncSetAttribute(gemm_dual, cudaFuncAttributeMaxDynamicSharedMemorySize,
                         GSMEM_D);
    cudaFuncSetAttribute(gemm_jk, cudaFuncAttributeMaxDynamicSharedMemorySize,
                         GSMEM_J);

    cudaStream_t s1;
    cudaStreamCreateWithFlags(&s1, cudaStreamNonBlocking);
    cudaEvent_t eStart, eCvt, eCsr, eEdge1, eJKa;
    cudaEventCreateWithFlags(&eStart, cudaEventDisableTiming);
    cudaEventCreateWithFlags(&eCvt,   cudaEventDisableTiming);
    cudaEventCreateWithFlags(&eCsr,   cudaEventDisableTiming);
    cudaEventCreateWithFlags(&eEdge1, cudaEventDisableTiming);
    cudaEventCreateWithFlags(&eJKa,   cudaEventDisableTiming);

    const int MT = (NN + 127) / 128;
    const int JT = (NN + 63) / 64;

    // fork: side stream runs the CSR build concurrently with cvt + gemm L1
    cudaEventRecord(eStart, 0);
    cudaStreamWaitEvent(s1, eStart, 0);
    init_hist_kernel<<<(NN + 255) / 256, 256, 0, s1>>>();
    hist_kernel<<<(EE + 255) / 256, 256, 0, s1>>>(ei);
    scan_kernel<<<1, 1024, 0, s1>>>();
    scatter_kernel<<<(ETOT + 255) / 256, 256, 0, s1>>>(ei);
    cudaEventRecord(eCsr, s1);

    // main stream: conversions + layer-1 GEMM
    {
        CvtJobs jobs;
        jobs.s[0] = x;   jobs.h[0] = xh;   jobs.l[0] = xlo;  jobs.n[0] = NN * HIDD;
        jobs.s[1] = Wl1; jobs.h[1] = Wl1h; jobs.l[1] = Wl1l; jobs.n[1] = HIDD * DD1;
        jobs.s[2] = Wr1; jobs.h[2] = Wr1h; jobs.l[2] = Wr1l; jobs.n[2] = HIDD * DD1;
        jobs.s[3] = Wl2; jobs.h[3] = Wl2h; jobs.l[3] = Wl2l; jobs.n[3] = DD1 * DD2;
        jobs.s[4] = Wr2; jobs.h[4] = Wr2h; jobs.l[4] = Wr2l; jobs.n[4] = DD1 * DD2;
        jobs.s[5] = Wjk; jobs.h[5] = Wjkh; jobs.l[5] = Wjkl; jobs.n[5] = 896 * HIDD;
        int gx = (NN * HIDD / 4 + 255) / 256;
        cvt_all_kernel<<<dim3(gx, 6), 256>>>(jobs);
    }
    cudaEventRecord(eCvt, 0);
    gemm_dual<<<dim3(8, MT), 256, GSMEM_D>>>(
        xh, xlo, Wl1h, Wl1l, Wr1h, Wr1l, bl1, br1, xl1, xr1,
        NN, HIDD, DD1, 4);

    // side stream: JK_x (chunks 0..3) in the idle window after CSR, under gemm L1
    cudaStreamWaitEvent(s1, eCvt, 0);
    gemm_jk<<<JT, 256, GSMEM_J, s1>>>(
        xh, xlo, h1h, h1l, h2h, h2l, Wjkh, Wjkl, bjk, out, NN, 0, 4, 0);

    // main: edge layer 1 (after CSR join)
    cudaStreamWaitEvent(0, eCsr, 0);
    gat_edge_kernel<2, 8><<<NN / 4, 256>>>(xl1, xr1, att1, bias1, h1h, h1l);
    cudaEventRecord(eEdge1, 0);

    // side stream: JK_h1 (chunks 4..19, accumulate) overlaps L2 phase
    cudaStreamWaitEvent(s1, eEdge1, 0);
    gemm_jk<<<JT, 256, GSMEM_J, s1>>>(
        xh, xlo, h1h, h1l, h2h, h2l, Wjkh, Wjkl, bjk, out, NN, 4, 16, 1);
    cudaEventRecord(eJKa, s1);

    // main stream: layer-2 GEMM + edge layer 2
    gemm_dual<<<dim3(4, MT), 256, GSMEM_D>>>(
        h1h, h1l, Wl2h, Wl2l, Wr2h, Wr2l, bl2, br2, xl2, xr2,
        NN, DD1, DD2, 2);
    gat_edge_kernel<1, 4><<<NN / 8, 256>>>(xl2, xr2, att2, bias2, h2h, h2l);

    // join JK_h1, then JK_h2 (chunks 20..27, accumulate into out)
    cudaStreamWaitEvent(0, eJKa, 0);
    gemm_jk<<<JT, 256, GSMEM_J>>>(
        xh, xlo, h1h, h1l, h2h, h2l, Wjkh, Wjkl, bjk, out, NN, 20, 8, 1);

    cudaEventDestroy(eStart);
    cudaEventDestroy(eCvt);
    cudaEventDestroy(eCsr);
    cudaEventDestroy(eEdge1);
    cudaEventDestroy(eJKa);
    cudaStreamDestroy(s1);
}

// round 17
// speedup vs baseline: 1.1013x; 1.0570x over previous
#include <cuda_runtime.h>
#include <cuda_bf16.h>
#include <cuda_fp16.h>
#include <math.h>
#include <stdint.h>

#define NN   20000
#define EE   320000
#define ETOT (EE + NN)
#define HIDD 128
#define DD1  512
#define DD2  256

typedef __nv_bfloat16 bf16;

// ---------------- device scratch --------------------------------------------
__device__ __half g_xl1[(size_t)NN * DD1];
__device__ __half g_xr1[(size_t)NN * DD1];
__device__ __half g_xl2[(size_t)NN * DD2];
__device__ __half g_xr2[(size_t)NN * DD2];
__device__ bf16  g_xh [(size_t)NN * HIDD];
__device__ bf16  g_xlo[(size_t)NN * HIDD];
__device__ bf16  g_h1h[(size_t)NN * DD1];
__device__ bf16  g_h1l[(size_t)NN * DD1];
__device__ bf16  g_h2h[(size_t)NN * DD2];
__device__ bf16  g_h2l[(size_t)NN * DD2];
__device__ bf16  g_Wl1h[HIDD * DD1], g_Wl1l[HIDD * DD1];
__device__ bf16  g_Wr1h[HIDD * DD1], g_Wr1l[HIDD * DD1];
__device__ bf16  g_Wl2h[DD1 * DD2],  g_Wl2l[DD1 * DD2];
__device__ bf16  g_Wr2h[DD1 * DD2],  g_Wr2l[DD1 * DD2];
__device__ bf16  g_Wjkh[896 * HIDD], g_Wjkl[896 * HIDD];
__device__ int   g_rowptr[NN + 1];
__device__ int   g_cursor[NN];
__device__ int   g_colsrc[ETOT];

// ---------------- CSR build -------------------------------------------------
__global__ void init_hist_kernel() {
    int i = blockIdx.x * blockDim.x + threadIdx.x;
    if (i < NN) g_cursor[i] = 1;   // self loop per node
}

__global__ void hist_kernel(const int* __restrict__ ei) {
    int e = blockIdx.x * blockDim.x + threadIdx.x;
    if (e < EE) atomicAdd(&g_cursor[ei[EE + e]], 1);
}

__global__ void scan_kernel() {
    const int PER = 20;
    __shared__ int sh[1024];
    int t = threadIdx.x;
    int base = t * PER;
    int loc[PER];
    int sum = 0;
    #pragma unroll
    for (int i = 0; i < PER; i++) {
        int idx = base + i;
        int v = (idx < NN) ? g_cursor[idx] : 0;
        loc[i] = v;
        sum += v;
    }
    sh[t] = sum;
    __syncthreads();
    #pragma unroll
    for (int off = 1; off < 1024; off <<= 1) {
        int v = (t >= off) ? sh[t - off] : 0;
        __syncthreads();
        sh[t] += v;
        __syncthreads();
    }
    int run = sh[t] - sum;
    #pragma unroll
    for (int i = 0; i < PER; i++) {
        int idx = base + i;
        if (idx < NN) { g_rowptr[idx] = run; g_cursor[idx] = run; }
        run += loc[i];
    }
    if (t == 1023) g_rowptr[NN] = sh[1023];
}

__global__ void scatter_kernel(const int* __restrict__ ei) {
    int t = blockIdx.x * blockDim.x + threadIdx.x;
    if (t < EE) {
        int s = ei[t];
        int d = ei[EE + t];
        int pos = atomicAdd(&g_cursor[d], 1);
        g_colsrc[pos] = s;
    } else if (t < ETOT) {
        int i = t - EE;
        int pos = atomicAdd(&g_cursor[i], 1);
        g_colsrc[pos] = i;
    }
}

// ---------------- fp32 -> bf16 hi/lo split, all sources in one launch -------
struct CvtJobs {
    const float* s[6];
    bf16* h[6];
    bf16* l[6];
    int   n[6];
};

__global__ void cvt_all_kernel(CvtJobs jobs) {
    int y = blockIdx.y;
    int n = jobs.n[y];
    int i = (blockIdx.x * blockDim.x + threadIdx.x) * 4;
    if (i >= n) return;
    const float* s = jobs.s[y];
    float4 v = *(const float4*)(s + i);
    bf16 hh[4], ll[4];
    hh[0] = __float2bfloat16_rn(v.x);
    hh[1] = __float2bfloat16_rn(v.y);
    hh[2] = __float2bfloat16_rn(v.z);
    hh[3] = __float2bfloat16_rn(v.w);
    ll[0] = __float2bfloat16_rn(v.x - __bfloat162float(hh[0]));
    ll[1] = __float2bfloat16_rn(v.y - __bfloat162float(hh[1]));
    ll[2] = __float2bfloat16_rn(v.z - __bfloat162float(hh[2]));
    ll[3] = __float2bfloat16_rn(v.w - __bfloat162float(hh[3]));
    *(uint2*)(jobs.h[y] + i) = *(uint2*)hh;
    *(uint2*)(jobs.l[y] + i) = *(uint2*)ll;
}

// ---------------- shared GEMM plumbing ---------------------------------------
__device__ __forceinline__ uint32_t smem_u32(const void* p) {
    return (uint32_t)__cvta_generic_to_shared(p);
}

__device__ __forceinline__ void cp16(uint32_t dst, const void* src, uint32_t sz) {
    asm volatile("cp.async.cg.shared.global [%0], [%1], 16, %2;"
                 :: "r"(dst), "l"(src), "r"(sz) : "memory");
}
#define CP_COMMIT() asm volatile("cp.async.commit_group;" ::: "memory")
#define CP_WAIT1()  asm volatile("cp.async.wait_group 1;" ::: "memory")

#define LDSM_X4(r, addr) \
    asm volatile("ldmatrix.sync.aligned.m8n8.x4.shared.b16 {%0,%1,%2,%3}, [%4];" \
        : "=r"((r)[0]), "=r"((r)[1]), "=r"((r)[2]), "=r"((r)[3]) : "r"(addr))

#define LDSM_X2T(r, addr) \
    asm volatile("ldmatrix.sync.aligned.m8n8.x2.trans.shared.b16 {%0,%1}, [%2];" \
        : "=r"((r)[0]), "=r"((r)[1]) : "r"(addr))

#define MMA16816(d, a, b) \
    asm volatile("mma.sync.aligned.m16n8k16.row.col.f32.bf16.bf16.f32 " \
        "{%0,%1,%2,%3},{%4,%5,%6,%7},{%8,%9},{%0,%1,%2,%3};" \
        : "+f"((d)[0]), "+f"((d)[1]), "+f"((d)[2]), "+f"((d)[3]) \
        : "r"((a)[0]), "r"((a)[1]), "r"((a)[2]), "r"((a)[3]), \
          "r"((b)[0]), "r"((b)[1]))

// ---------------- dual-output bf16 GEMM (3-term split), fp16 out ------------
#define STG_D   32768
#define GSMEM_D (3 * STG_D)

__global__ __launch_bounds__(256, 2)
void gemm_dual(const bf16* __restrict__ Ah, const bf16* __restrict__ Al,
               const bf16* __restrict__ B0h, const bf16* __restrict__ B0l,
               const bf16* __restrict__ B1h, const bf16* __restrict__ B1l,
               const float* __restrict__ b0, const float* __restrict__ b1,
               __half* __restrict__ C0, __half* __restrict__ C1,
               int M, int K, int Nhalf, int nHalfTiles)
{
    extern __shared__ char sm[];
    const uint32_t sb = smem_u32(sm);
    const int tid = threadIdx.x;
    const int lane = tid & 31, wid = tid >> 5;
    const int wm = wid & 1, wn = wid >> 1;
    const int bm = blockIdx.y * 128;
    const int half = (blockIdx.x >= nHalfTiles);
    const int bn = (blockIdx.x - half * nHalfTiles) * 128;

    const bf16* Bh = half ? B1h : B0h;
    const bf16* Bl = half ? B1l : B0l;
    const float* bias = half ? b1 : b0;
    __half* C = half ? C1 : C0;

    const int l15 = lane & 15;
    const uint32_t xorq = (uint32_t)(lane & 7) << 4;
    const uint32_t hi16 = (uint32_t)(lane >> 4) * 16;

    uint32_t adst[4], asz[4];
    const bf16* asrc[4];
    uint32_t bdst[4];
    const bf16* bsrc[4];
    #pragma unroll
    for (int i = 0; i < 4; i++) {
        int id = tid + i * 256;
        int arid = id >> 3, aseg = id & 7;
        int apart = aseg >> 2, ac4 = aseg & 3;
        adst[i] = (uint32_t)(arid * 128) +
                  (((uint32_t)(aseg * 16)) ^ ((uint32_t)(arid & 7) << 4));
        int grow = bm + arid;
        asz[i] = (grow < M) ? 16u : 0u;
        asrc[i] = (apart ? Al : Ah) + (size_t)min(grow, M - 1) * K + ac4 * 8;

        int bkrow = id >> 4, bc = id & 15;
        int bpart = bkrow >> 5, bkl = bkrow & 31;
        bdst[i] = 16384u + (uint32_t)(bkrow * 256) +
                  (((uint32_t)(bc * 16)) ^ ((uint32_t)(bkl & 7) << 4));
        bsrc[i] = (bpart ? Bl : Bh) + (size_t)bkl * Nhalf + bn + bc * 8;
    }

    const int nch = K >> 5;
    const size_t aStep = 32;
    const size_t bStep = (size_t)32 * Nhalf;

    #pragma unroll
    for (int s = 0; s < 2; s++) {
        if (s < nch) {
            uint32_t base = sb + s * STG_D;
            #pragma unroll
            for (int i = 0; i < 4; i++)
                cp16(base + adst[i], asrc[i] + (size_t)s * aStep, asz[i]);
            #pragma unroll
            for (int i = 0; i < 4; i++)
                cp16(base + bdst[i], bsrc[i] + (size_t)s * bStep, 16);
        }
        CP_COMMIT();
    }

    float acc[4][4][4];
    #pragma unroll
    for (int mi = 0; mi < 4; mi++)
        #pragma unroll
        for (int ni = 0; ni < 4; ni++)
            #pragma unroll
            for (int r = 0; r < 4; r++) acc[mi][ni][r] = 0.f;

    uint32_t aRowRel[4];
    #pragma unroll
    for (int mi = 0; mi < 4; mi++)
        aRowRel[mi] = (uint32_t)((wm * 64 + mi * 16 + l15) * 128);
    uint32_t bColRel[4];
    #pragma unroll
    for (int ni = 0; ni < 4; ni++)
        bColRel[ni] = ((uint32_t)((wn * 32 + ni * 8) * 2)) ^ xorq;

    for (int kc = 0; kc < nch; kc++) {
        CP_WAIT1();
        __syncthreads();
        int pf = kc + 2;
        if (pf < nch) {
            uint32_t base = sb + (pf % 3) * STG_D;
            #pragma unroll
            for (int i = 0; i < 4; i++)
                cp16(base + adst[i], asrc[i] + (size_t)pf * aStep, asz[i]);
            #pragma unroll
            for (int i = 0; i < 4; i++)
                cp16(base + bdst[i], bsrc[i] + (size_t)pf * bStep, 16);
        }
        CP_COMMIT();

        const uint32_t sA = sb + (kc % 3) * STG_D;
        const uint32_t sB = sA + 16384;

        #pragma unroll
        for (int ks = 0; ks < 2; ks++) {
            uint32_t acolH = ((uint32_t)(ks * 32) + hi16) ^ xorq;
            uint32_t acolL = ((uint32_t)(64 + ks * 32) + hi16) ^ xorq;
            uint32_t browH = sB + (uint32_t)((ks * 16 + l15) * 256);
            uint32_t browL = browH + 32 * 256;

            uint32_t ah[4][4], bh[4][2];
            #pragma unroll
            for (int mi = 0; mi < 4; mi++)
                LDSM_X4(ah[mi], sA + aRowRel[mi] + acolH);
            #pragma unroll
            for (int ni = 0; ni < 4; ni++)
                LDSM_X2T(bh[ni], browH + bColRel[ni]);
            #pragma unroll
            for (int mi = 0; mi < 4; mi++)
                #pragma unroll
                for (int ni = 0; ni < 4; ni++)
                    MMA16816(acc[mi][ni], ah[mi], bh[ni]);
            {
                uint32_t bl[4][2];
                #pragma unroll
                for (int ni = 0; ni < 4; ni++)
                    LDSM_X2T(bl[ni], browL + bColRel[ni]);
                #pragma unroll
                for (int mi = 0; mi < 4; mi++)
                    #pragma unroll
                    for (int ni = 0; ni < 4; ni++)
                        MMA16816(acc[mi][ni], ah[mi], bl[ni]);
            }
            {
                uint32_t al[4][4];
                #pragma unroll
                for (int mi = 0; mi < 4; mi++)
                    LDSM_X4(al[mi], sA + aRowRel[mi] + acolL);
                #pragma unroll
                for (int mi = 0; mi < 4; mi++)
                    #pragma unroll
                    for (int ni = 0; ni < 4; ni++)
                        MMA16816(acc[mi][ni], al[mi], bh[ni]);
            }
        }
    }

    const int row0 = bm + wm * 64 + (lane >> 2);
    const int col0 = bn + wn * 32 + (lane & 3) * 2;
    #pragma unroll
    for (int mi = 0; mi < 4; mi++) {
        #pragma unroll
        for (int h2 = 0; h2 < 2; h2++) {
            int row = row0 + mi * 16 + h2 * 8;
            if (row >= M) continue;
            __half* crow = C + (size_t)row * Nhalf;
            #pragma unroll
            for (int ni = 0; ni < 4; ni++) {
                int col = col0 + ni * 8;
                float2 b = *(const float2*)&bias[col];
                float vx = acc[mi][ni][h2 * 2 + 0] + b.x;
                float vy = acc[mi][ni][h2 * 2 + 1] + b.y;
                *(__half2*)&crow[col] = __floats2half2_rn(vx, vy);
            }
        }
    }
}

// ---------------- JK GEMM over chunk range [cbeg, cbeg+nch) -----------------
#define STG_J   24576
#define GSMEM_J (3 * STG_J)

__global__ __launch_bounds__(256, 2)
void gemm_jk(const bf16* __restrict__ xh,  const bf16* __restrict__ xlo,
             const bf16* __restrict__ h1h, const bf16* __restrict__ h1l,
             const bf16* __restrict__ h2h, const bf16* __restrict__ h2l,
             const bf16* __restrict__ Wh,  const bf16* __restrict__ Wl,
             const float* __restrict__ bias, float* __restrict__ C, int M,
             int cbeg, int nch, int accumulate)
{
    extern __shared__ char sm[];
    const uint32_t sb = smem_u32(sm);
    const int tid = threadIdx.x;
    const int lane = tid & 31, wid = tid >> 5;
    const int wm = wid & 1, wn = wid >> 1;
    const int bm = blockIdx.x * 64;
    const int N = HIDD;

    const int l15 = lane & 15;
    const uint32_t xorq = (uint32_t)(lane & 7) << 4;
    const uint32_t hi16 = (uint32_t)(lane >> 4) * 16;

    int arid[2], apart[2], ac4[2];
    uint32_t adst[2], asz[2];
    int agrow[2];
    #pragma unroll
    for (int i = 0; i < 2; i++) {
        int id = tid + i * 256;
        arid[i] = id >> 3;
        int aseg = id & 7;
        apart[i] = aseg >> 2;
        ac4[i] = aseg & 3;
        adst[i] = (uint32_t)(arid[i] * 128) +
                  (((uint32_t)(aseg * 16)) ^ ((uint32_t)(arid[i] & 7) << 4));
        agrow[i] = min(bm + arid[i], M - 1);
        asz[i] = (bm + arid[i] < M) ? 16u : 0u;
    }
    uint32_t bdst[4];
    int bpart[4], bkl[4], bc[4];
    #pragma unroll
    for (int i = 0; i < 4; i++) {
        int id = tid + i * 256;
        int bkrow = id >> 4;
        bc[i] = id & 15;
        bpart[i] = bkrow >> 5;
        bkl[i] = bkrow & 31;
        bdst[i] = 8192u + (uint32_t)(bkrow * 256) +
                  (((uint32_t)(bc[i] * 16)) ^ ((uint32_t)(bkl[i] & 7) << 4));
    }

    auto issue = [&](int c, uint32_t base) {
        const bf16 *Ah_, *Al_;
        int Kseg, coff;
        if (c < 4)       { Ah_ = xh;  Al_ = xlo; Kseg = HIDD; coff = c; }
        else if (c < 20) { Ah_ = h1h; Al_ = h1l; Kseg = DD1;  coff = c - 4; }
        else             { Ah_ = h2h; Al_ = h2l; Kseg = DD2;  coff = c - 20; }
        #pragma unroll
        for (int i = 0; i < 2; i++) {
            const bf16* src = (apart[i] ? Al_ : Ah_) +
                              (size_t)agrow[i] * Kseg + coff * 32 + ac4[i] * 8;
            cp16(base + adst[i], src, asz[i]);
        }
        #pragma unroll
        for (int i = 0; i < 4; i++) {
            const bf16* src = (bpart[i] ? Wl : Wh) +
                              (size_t)(c * 32 + bkl[i]) * N + bc[i] * 8;
            cp16(base + bdst[i], src, 16);
        }
    };

    #pragma unroll
    for (int s = 0; s < 2; s++) {
        if (s < nch) issue(cbeg + s, sb + s * STG_J);
        CP_COMMIT();
    }

    float acc[2][4][4];
    #pragma unroll
    for (int mi = 0; mi < 2; mi++)
        #pragma unroll
        for (int ni = 0; ni < 4; ni++)
            #pragma unroll
            for (int r = 0; r < 4; r++) acc[mi][ni][r] = 0.f;

    uint32_t aRowRel[2];
    #pragma unroll
    for (int mi = 0; mi < 2; mi++)
        aRowRel[mi] = (uint32_t)((wm * 32 + mi * 16 + l15) * 128);
    uint32_t bColRel[4];
    #pragma unroll
    for (int ni = 0; ni < 4; ni++)
        bColRel[ni] = ((uint32_t)((wn * 32 + ni * 8) * 2)) ^ xorq;

    for (int kc = 0; kc < nch; kc++) {
        CP_WAIT1();
        __syncthreads();
        int pf = kc + 2;
        if (pf < nch) issue(cbeg + pf, sb + (pf % 3) * STG_J);
        CP_COMMIT();

        const uint32_t sA = sb + (kc % 3) * STG_J;
        const uint32_t sB = sA + 8192;

        #pragma unroll
        for (int ks = 0; ks < 2; ks++) {
            uint32_t acolH = ((uint32_t)(ks * 32) + hi16) ^ xorq;
            uint32_t acolL = ((uint32_t)(64 + ks * 32) + hi16) ^ xorq;
            uint32_t browH = sB + (uint32_t)((ks * 16 + l15) * 256);
            uint32_t browL = browH + 32 * 256;

            uint32_t ah[2][4], bh[4][2];
            #pragma unroll
            for (int mi = 0; mi < 2; mi++)
                LDSM_X4(ah[mi], sA + aRowRel[mi] + acolH);
            #pragma unroll
            for (int ni = 0; ni < 4; ni++)
                LDSM_X2T(bh[ni], browH + bColRel[ni]);
            #pragma unroll
            for (int mi = 0; mi < 2; mi++)
                #pragma unroll
                for (int ni = 0; ni < 4; ni++)
                    MMA16816(acc[mi][ni], ah[mi], bh[ni]);
            {
                uint32_t bl[4][2];
                #pragma unroll
                for (int ni = 0; ni < 4; ni++)
                    LDSM_X2T(bl[ni], browL + bColRel[ni]);
                #pragma unroll
                for (int mi = 0; mi < 2; mi++)
                    #pragma unroll
                    for (int ni = 0; ni < 4; ni++)
                        MMA16816(acc[mi][ni], ah[mi], bl[ni]);
            }
            {
                uint32_t al[2][4];
                #pragma unroll
                for (int mi = 0; mi < 2; mi++)
                    LDSM_X4(al[mi], sA + aRowRel[mi] + acolL);
                #pragma unroll
                for (int mi = 0; mi < 2; mi++)
                    #pragma unroll
                    for (int ni = 0; ni < 4; ni++)
                        MMA16816(acc[mi][ni], al[mi], bh[ni]);
            }
        }
    }

    const int row0 = bm + wm * 32 + (lane >> 2);
    const int col0 = wn * 32 + (lane & 3) * 2;
    #pragma unroll
    for (int mi = 0; mi < 2; mi++) {
        #pragma unroll
        for (int half = 0; half < 2; half++) {
            int row = row0 + mi * 16 + half * 8;
            if (row >= M) continue;
            float* crow = C + (size_t)row * N;
            #pragma unroll
            for (int ni = 0; ni < 4; ni++) {
                int col = col0 + ni * 8;
                float2 v;
                v.x = acc[mi][ni][half * 2 + 0];
                v.y = acc[mi][ni][half * 2 + 1];
                if (accumulate) {
                    float2 o = *(float2*)&crow[col];
                    v.x += o.x; v.y += o.y;
                } else {
                    float2 b = *(const float2*)&bias[col];
                    v.x += b.x; v.y += b.y;
                }
                *(float2*)&crow[col] = v;
            }
        }
    }
}

// ---------------- fused GATv2 edge phase: LPH lanes/head, 8 ch/lane ---------
// Lane gathers one uint4 (8 fp16); LPH-lane groups reduce the head logit;
// unstabilized softmax; depth-1 software prefetch.
template<int WPN, int LPH>
__global__ __launch_bounds__(256)
void gat_edge_kernel(const __half* __restrict__ xl,
                     const __half* __restrict__ xr,
                     const float* __restrict__ att,
                     const float* __restrict__ bias,
                     bf16* __restrict__ outh,
                     bf16* __restrict__ outl)
{
    constexpr int D   = WPN * 256;
    constexpr int NPB = 8 / WPN;          // nodes per 256-thread block
    const int w    = threadIdx.x >> 5;
    const int lane = threadIdx.x & 31;
    const int node = blockIdx.x * NPB + w / WPN;
    const int sub  = w % WPN;
    const int cbase = sub * 256 + lane * 8;

    float attv[8], xrv[8], acc[8];
    {
        uint4 rx = *(const uint4*)(xr + (size_t)node * D + cbase);
        const __half2* hp = (const __half2*)&rx;
        #pragma unroll
        for (int q = 0; q < 4; q++) {
            float2 f = __half22float2(hp[q]);
            xrv[2 * q] = f.x; xrv[2 * q + 1] = f.y;
        }
        #pragma unroll
        for (int k = 0; k < 8; k++) { attv[k] = att[cbase + k]; acc[k] = 0.f; }
    }

    const int beg = g_rowptr[node], end = g_rowptr[node + 1];
    float s = 0.f;

    uint4 cur, nxt;
    cur = *(const uint4*)(xl + (size_t)g_colsrc[beg] * D + cbase);
    for (int j = beg; j < end; j++) {
        if (j + 1 < end)
            nxt = *(const uint4*)(xl + (size_t)g_colsrc[j + 1] * D + cbase);
        float x[8];
        {
            const __half2* hp = (const __half2*)&cur;
            #pragma unroll
            for (int q = 0; q < 4; q++) {
                float2 f = __half22float2(hp[q]);
                x[2 * q] = f.x; x[2 * q + 1] = f.y;
            }
        }
        float e = 0.f;
        #pragma unroll
        for (int k = 0; k < 8; k++) {
            float t = x[k] + xrv[k];
            t = fmaxf(t, 0.2f * t);          // leaky_relu(0.2), exact
            e = fmaf(t, attv[k], e);
        }
        #pragma unroll
        for (int o = 1; o < LPH; o <<= 1)    // head logit (LPH-lane group)
            e += __shfl_xor_sync(0xffffffffu, e, o);
        float wgt = __expf(e);
        s += wgt;
        #pragma unroll
        for (int k = 0; k < 8; k++)
            acc[k] = fmaf(wgt, x[k], acc[k]);
        cur = nxt;
    }

    float inv = 1.0f / s;
    bf16 oh[8], ol[8];
    #pragma unroll
    for (int k = 0; k < 8; k++) {
        float v = acc[k] * inv + bias[cbase + k];
        v = (v > 0.f) ? v : expm1f(v);       // elu
        oh[k] = __float2bfloat16_rn(v);
        ol[k] = __float2bfloat16_rn(v - __bfloat162float(oh[k]));
    }
    *(uint4*)(outh + (size_t)node * D + cbase) = *(uint4*)oh;
    *(uint4*)(outl + (size_t)node * D + cbase) = *(uint4*)ol;
}

// ---------------- launch ----------------------------------------------------
extern "C" void kernel_launch(void* const* d_in, const int* in_sizes, int n_in,
                              void* d_out, int out_size)
{
    const float* x     = (const float*)d_in[0];
    const int*   ei    = (const int*)  d_in[1];
    const float* Wl1   = (const float*)d_in[2];
    const float* bl1   = (const float*)d_in[3];
    const float* Wr1   = (const float*)d_in[4];
    const float* br1   = (const float*)d_in[5];
    const float* att1  = (const float*)d_in[6];
    const float* bias1 = (const float*)d_in[7];
    const float* Wl2   = (const float*)d_in[8];
    const float* bl2   = (const float*)d_in[9];
    const float* Wr2   = (const float*)d_in[10];
    const float* br2   = (const float*)d_in[11];
    const float* att2  = (const float*)d_in[12];
    const float* bias2 = (const float*)d_in[13];
    const float* Wjk   = (const float*)d_in[14];
    const float* bjk   = (const float*)d_in[15];
    float* out = (float*)d_out;

    __half *xl1, *xr1, *xl2, *xr2;
    bf16 *xh, *xlo, *h1h, *h1l, *h2h, *h2l;
    bf16 *Wl1h, *Wl1l, *Wr1h, *Wr1l, *Wl2h, *Wl2l, *Wr2h, *Wr2l, *Wjkh, *Wjkl;
    cudaGetSymbolAddress((void**)&xl1,  g_xl1);
    cudaGetSymbolAddress((void**)&xr1,  g_xr1);
    cudaGetSymbolAddress((void**)&xl2,  g_xl2);
    cudaGetSymbolAddress((void**)&xr2,  g_xr2);
    cudaGetSymbolAddress((void**)&xh,   g_xh);
    cudaGetSymbolAddress((void**)&xlo,  g_xlo);
    cudaGetSymbolAddress((void**)&h1h,  g_h1h);
    cudaGetSymbolAddress((void**)&h1l,  g_h1l);
    cudaGetSymbolAddress((void**)&h2h,  g_h2h);
    cudaGetSymbolAddress((void**)&h2l,  g_h2l);
    cudaGetSymbolAddress((void**)&Wl1h, g_Wl1h);
    cudaGetSymbolAddress((void**)&Wl1l, g_Wl1l);
    cudaGetSymbolAddress((void**)&Wr1h, g_Wr1h);
    cudaGetSymbolAddress((void**)&Wr1l, g_Wr1l);
    cudaGetSymbolAddress((void**)&Wl2h, g_Wl2h);
    cudaGetSymbolAddress((void**)&Wl2l, g_Wl2l);
    cudaGetSymbolAddress((void**)&Wr2h, g_Wr2h);
    cudaGetSymbolAddress((void**)&Wr2l, g_Wr2l);
    cudaGetSymbolAddress((void**)&Wjkh, g_Wjkh);
    cudaGetSymbolAddress((void**)&Wjkl, g_Wjkl);

    cudaFuncSetAttribute(gemm_dual, cudaFuncAttributeMaxDynamicSharedMemorySize,
                         GSMEM_D);
    cudaFuncSetAttribute(gemm_jk, cudaFuncAttributeMaxDynamicSharedMemorySize,
                         GSMEM_J);

    cudaStream_t s1;
    cudaStreamCreateWithFlags(&s1, cudaStreamNonBlocking);
    cudaEvent_t eStart, eCsr, eEdge1, eJKa;
    cudaEventCreateWithFlags(&eStart, cudaEventDisableTiming);
    cudaEventCreateWithFlags(&eCsr,   cudaEventDisableTiming);
    cudaEventCreateWithFlags(&eEdge1, cudaEventDisableTiming);
    cudaEventCreateWithFlags(&eJKa,   cudaEventDisableTiming);

    const int MT = (NN + 127) / 128;

    // fork: side stream runs the CSR build concurrently with cvt + gemm L1
    cudaEventRecord(eStart, 0);
    cudaStreamWaitEvent(s1, eStart, 0);
    init_hist_kernel<<<(NN + 255) / 256, 256, 0, s1>>>();
    hist_kernel<<<(EE + 255) / 256, 256, 0, s1>>>(ei);
    scan_kernel<<<1, 1024, 0, s1>>>();
    scatter_kernel<<<(ETOT + 255) / 256, 256, 0, s1>>>(ei);
    cudaEventRecord(eCsr, s1);

    // main stream: conversions + layer-1 GEMM
    {
        CvtJobs jobs;
        jobs.s[0] = x;   jobs.h[0] = xh;   jobs.l[0] = xlo;  jobs.n[0] = NN * HIDD;
        jobs.s[1] = Wl1; jobs.h[1] = Wl1h; jobs.l[1] = Wl1l; jobs.n[1] = HIDD * DD1;
        jobs.s[2] = Wr1; jobs.h[2] = Wr1h; jobs.l[2] = Wr1l; jobs.n[2] = HIDD * DD1;
        jobs.s[3] = Wl2; jobs.h[3] = Wl2h; jobs.l[3] = Wl2l; jobs.n[3] = DD1 * DD2;
        jobs.s[4] = Wr2; jobs.h[4] = Wr2h; jobs.l[4] = Wr2l; jobs.n[4] = DD1 * DD2;
        jobs.s[5] = Wjk; jobs.h[5] = Wjkh; jobs.l[5] = Wjkl; jobs.n[5] = 896 * HIDD;
        int gx = (NN * HIDD / 4 + 255) / 256;
        cvt_all_kernel<<<dim3(gx, 6), 256>>>(jobs);
    }
    gemm_dual<<<dim3(8, MT), 256, GSMEM_D>>>(
        xh, xlo, Wl1h, Wl1l, Wr1h, Wr1l, bl1, br1, xl1, xr1,
        NN, HIDD, DD1, 4);

    // join CSR, then edge layer 1 (2 warps/node; C=64 -> 8 lanes/head)
    cudaStreamWaitEvent(0, eCsr, 0);
    gat_edge_kernel<2, 8><<<NN / 4, 256>>>(xl1, xr1, att1, bias1, h1h, h1l);
    cudaEventRecord(eEdge1, 0);

    // side stream: JK_a (x + h1 segments, chunks 0..19) overlaps L2 phase
    cudaStreamWaitEvent(s1, eEdge1, 0);
    gemm_jk<<<(NN + 63) / 64, 256, GSMEM_J, s1>>>(
        xh, xlo, h1h, h1l, h2h, h2l, Wjkh, Wjkl, bjk, out, NN, 0, 20, 0);
    cudaEventRecord(eJKa, s1);

    // main stream: layer-2 GEMM + edge layer 2 (1 warp/node; C=32 -> 4 lanes/head)
    gemm_dual<<<dim3(4, MT), 256, GSMEM_D>>>(
        h1h, h1l, Wl2h, Wl2l, Wr2h, Wr2l, bl2, br2, xl2, xr2,
        NN, DD1, DD2, 2);
    gat_edge_kernel<1, 4><<<NN / 8, 256>>>(xl2, xr2, att2, bias2, h2h, h2l);

    // join JK_a, then JK_b (h2 segment, chunks 20..27, accumulate into out)
    cudaStreamWaitEvent(0, eJKa, 0);
    gemm_jk<<<(NN + 63) / 64, 256, GSMEM_J>>>(
        xh, xlo, h1h, h1l, h2h, h2l, Wjkh, Wjkl, bjk, out, NN, 20, 8, 1);

    cudaEventDestroy(eStart);
    cudaEventDestroy(eCsr);
    cudaEventDestroy(eEdge1);
    cudaEventDestroy(eJKa);
    cudaStreamDestroy(s1);
}